// round 5
// baseline (speedup 1.0000x reference)
#include <cuda_runtime.h>

#define NT 128
#define NH 8
#define NL 3
#define LOG2E 1.4426950408889634f

#define O_WK  0
#define O_WQ  24
#define O_WV  48
#define O_WP  72
#define O_BP  96
#define O_W1  99
#define O_B1  111
#define O_W2  123
#define O_B2  135
#define O_WLM 138
#define O_BLM 139
#define NWTS  140

__device__ __forceinline__ float ex2(float x) {
    float y;
    asm("ex2.approx.ftz.f32 %0, %1;" : "=f"(y) : "f"(x));
    return y;
}

struct OS { float m, d, n; };
__device__ __forceinline__ OS comb(OS a, OS b) {
    float mx = fmaxf(a.m, b.m);
    float mn = fminf(a.m, b.m);
    float e  = ex2(mn - mx);
    bool  bl = a.m < b.m;
    float sa = bl ? e : 1.0f;
    float sb = bl ? 1.0f : e;
    OS r; r.m = mx; r.d = fmaf(a.d, sa, b.d * sb); r.n = fmaf(a.n, sa, b.n * sb);
    return r;
}

__global__ __launch_bounds__(128) void cat_kernel(
    const float* __restrict__ X,
    const float* __restrict__ wk, const float* __restrict__ wq, const float* __restrict__ wv,
    const float* __restrict__ Wp, const float* __restrict__ bp,
    const float* __restrict__ W1, const float* __restrict__ b1,
    const float* __restrict__ W2, const float* __restrict__ b2,
    const float* __restrict__ w_lm, const float* __restrict__ b_lm,
    float* __restrict__ out)
{
    __shared__ float W[NWTS];

    const int tid = threadIdx.x;
    const int wr  = tid >> 5;          // warp id = batch-within-block
    const int lid = tid & 31;
    const int batch = blockIdx.x * 4 + wr;

    for (int i = tid; i < NWTS; i += 128) {
        float v;
        if      (i < 24)  v = wk[i];
        else if (i < 48)  v = wq[i - 24];
        else if (i < 72)  v = wv[i - 48];
        else if (i < 96)  v = Wp[i - 72];
        else if (i < 99)  v = bp[i - 96];
        else if (i < 111) v = W1[i - 99];
        else if (i < 123) v = b1[i - 111];
        else if (i < 135) v = W2[i - 123];
        else if (i < 138) v = b2[i - 135];
        else if (i == 138) v = w_lm[0];
        else               v = b_lm[0];
        W[i] = v;
    }

    // x for this batch lives in registers across all layers
    float4 xv = reinterpret_cast<const float4*>(X + batch * NT)[lid];
    float x0 = xv.x, x1 = xv.y, x2 = xv.z, x3 = xv.w;
    __syncthreads();   // the only block barrier

    #pragma unroll
    for (int l = 0; l < NL; ++l) {
        float u0 = x0*x0, u1 = x1*x1, u2 = x2*x2, u3 = x3*x3;

        // one butterfly max/min of u serves all 8 heads
        float umx = fmaxf(fmaxf(u0, u1), fmaxf(u2, u3));
        float umn = fminf(fminf(u0, u1), fminf(u2, u3));
        #pragma unroll
        for (int o = 16; o > 0; o >>= 1) {
            umx = fmaxf(umx, __shfl_xor_sync(0xffffffffu, umx, o));
            umn = fminf(umn, __shfl_xor_sync(0xffffffffu, umn, o));
        }

        float y0 = W[O_BP + l], y1 = y0, y2 = y0, y3 = y0;

        #pragma unroll
        for (int h = 0; h < NH; ++h) {
            const float c    = W[O_WK + l*NH + h] * W[O_WQ + l*NH + h] * LOG2E;
            const float coef = W[O_WV + l*NH + h] * W[O_WP + l*NH + h];
            const float shi  = (c > 0.0f) ? c * umx : c * umn;   // row max of scores
            const float slo  = (c > 0.0f) ? c * umn : c * umx;   // row min

            float h0, h1v, h2v, h3v;

            if (shi - slo < 120.0f) {
                // ---- single-window additive scan (terms >= 2^-57, no FTZ) ----
                const float K = shi - 63.0f;
                float e0 = ex2(fmaf(c, u0, -K));
                float e1 = ex2(fmaf(c, u1, -K));
                float e2 = ex2(fmaf(c, u2, -K));
                float e3 = ex2(fmaf(c, u3, -K));
                float n0 = e0*x0, n1 = e1*x1, n2 = e2*x2, n3 = e3*x3;

                float d01 = e0+e1, d012 = d01+e2, dT = d012+e3;
                float m01 = n0+n1, m012 = m01+n2, mT = m012+n3;

                float sd = dT, sn = mT;
                #pragma unroll
                for (int o = 1; o < 32; o <<= 1) {
                    float ud = __shfl_up_sync(0xffffffffu, sd, o);
                    float un = __shfl_up_sync(0xffffffffu, sn, o);
                    if (lid >= o) { sd += ud; sn += un; }
                }
                float Pd = __shfl_up_sync(0xffffffffu, sd, 1);
                float Pn = __shfl_up_sync(0xffffffffu, sn, 1);
                if (lid == 0) { Pd = 0.0f; Pn = 0.0f; }

                h0  = (lid == 0) ? 0.0f : __fdividef(Pn, Pd);
                h1v = __fdividef(Pn + n0,   Pd + e0);
                h2v = __fdividef(Pn + m01,  Pd + d01);
                h3v = __fdividef(Pn + m012, Pd + d012);
            } else {
                // ---- exact online-softmax monoid fallback (any range) ----
                OS a0 = { c*u0, 1.0f, x0 };
                OS a1 = comb(a0, { c*u1, 1.0f, x1 });
                OS a2 = comb(a1, { c*u2, 1.0f, x2 });
                OS a3 = comb(a2, { c*u3, 1.0f, x3 });
                OS agg = a3;
                #pragma unroll
                for (int o = 1; o < 32; o <<= 1) {
                    OS up;
                    up.m = __shfl_up_sync(0xffffffffu, agg.m, o);
                    up.d = __shfl_up_sync(0xffffffffu, agg.d, o);
                    up.n = __shfl_up_sync(0xffffffffu, agg.n, o);
                    if (lid >= o) agg = comb(up, agg);
                }
                OS P;
                P.m = __shfl_up_sync(0xffffffffu, agg.m, 1);
                P.d = __shfl_up_sync(0xffffffffu, agg.d, 1);
                P.n = __shfl_up_sync(0xffffffffu, agg.n, 1);
                if (lid == 0) { P.m = -1e30f; P.d = 0.0f; P.n = 0.0f; }
                OS q1 = comb(P, a0);
                OS q2 = comb(P, a1);
                OS q3 = comb(P, a2);
                h0  = (lid == 0) ? 0.0f : __fdividef(P.n, P.d);
                h1v = __fdividef(q1.n, q1.d);
                h2v = __fdividef(q2.n, q2.d);
                h3v = __fdividef(q3.n, q3.d);
            }

            // fold projection in registers: y += ho * Wp  (ho = wv * ratio)
            y0 = fmaf(h0,  coef, y0);
            y1 = fmaf(h1v, coef, y1);
            y2 = fmaf(h2v, coef, y2);
            y3 = fmaf(h3v, coef, y3);
        }

        // ---- FF per position, register-local ----
        const float b2v = W[O_B2 + l];
        const float w10 = W[O_W1 + l*4 + 0], w11 = W[O_W1 + l*4 + 1], w12 = W[O_W1 + l*4 + 2], w13 = W[O_W1 + l*4 + 3];
        const float b10 = W[O_B1 + l*4 + 0], b11 = W[O_B1 + l*4 + 1], b12 = W[O_B1 + l*4 + 2], b13 = W[O_B1 + l*4 + 3];
        const float w20 = W[O_W2 + l*4 + 0], w21 = W[O_W2 + l*4 + 1], w22 = W[O_W2 + l*4 + 2], w23 = W[O_W2 + l*4 + 3];
        #define FF(y_) ({                                                     \
            float f_ = b2v;                                                   \
            f_ = fmaf(fmaxf(fmaf((y_), w10, b10), 0.0f), w20, f_);            \
            f_ = fmaf(fmaxf(fmaf((y_), w11, b11), 0.0f), w21, f_);            \
            f_ = fmaf(fmaxf(fmaf((y_), w12, b12), 0.0f), w22, f_);            \
            f_ = fmaf(fmaxf(fmaf((y_), w13, b13), 0.0f), w23, f_);            \
            (y_) + f_; })
        x0 = FF(y0); x1 = FF(y1); x2 = FF(y2); x3 = FF(y3);
        #undef FF
    }

    const float wl = W[O_WLM], bl = W[O_BLM];
    float4 ov;
    ov.x = fmaf(x0, wl, bl);
    ov.y = fmaf(x1, wl, bl);
    ov.z = fmaf(x2, wl, bl);
    ov.w = fmaf(x3, wl, bl);
    reinterpret_cast<float4*>(out + batch * NT)[lid] = ov;
}

extern "C" void kernel_launch(void* const* d_in, const int* in_sizes, int n_in,
                              void* d_out, int out_size) {
    (void)in_sizes; (void)n_in; (void)out_size;
    cat_kernel<<<128, 128>>>(
        (const float*)d_in[0],  // X
        (const float*)d_in[1],  // wk
        (const float*)d_in[2],  // wq
        (const float*)d_in[3],  // wv
        (const float*)d_in[4],  // Wp
        (const float*)d_in[5],  // bp
        (const float*)d_in[6],  // W1
        (const float*)d_in[7],  // b1
        (const float*)d_in[8],  // W2
        (const float*)d_in[9],  // b2
        (const float*)d_in[10], // w_lm
        (const float*)d_in[11], // b_lm
        (float*)d_out);
}

// round 6
// speedup vs baseline: 1.3902x; 1.3902x over previous
#include <cuda_runtime.h>

#define NT 128
#define NH 8
#define NL 3
#define LOG2E 1.4426950408889634f

#define O_WK  0
#define O_WQ  24
#define O_WV  48
#define O_WP  72
#define O_BP  96
#define O_W1  99
#define O_B1  111
#define O_W2  123
#define O_B2  135
#define O_WLM 138
#define O_BLM 139
#define NWTS  140

__device__ __forceinline__ float ex2(float x) {
    float y;
    asm("ex2.approx.ftz.f32 %0, %1;" : "=f"(y) : "f"(x));
    return y;
}

struct OS { float m, d, n; };
__device__ __forceinline__ OS comb(OS a, OS b) {
    float mx = fmaxf(a.m, b.m);
    float mn = fminf(a.m, b.m);
    float e  = ex2(mn - mx);
    bool  bl = a.m < b.m;
    float sa = bl ? e : 1.0f;
    float sb = bl ? 1.0f : e;
    OS r; r.m = mx; r.d = fmaf(a.d, sa, b.d * sb); r.n = fmaf(a.n, sa, b.n * sb);
    return r;
}

__global__ __launch_bounds__(64) void cat_kernel(
    const float* __restrict__ X,
    const float* __restrict__ wk, const float* __restrict__ wq, const float* __restrict__ wv,
    const float* __restrict__ Wp, const float* __restrict__ bp,
    const float* __restrict__ W1, const float* __restrict__ b1,
    const float* __restrict__ W2, const float* __restrict__ b2,
    const float* __restrict__ w_lm, const float* __restrict__ b_lm,
    float* __restrict__ out)
{
    __shared__ float  W[NWTS];
    __shared__ float4 py[2][2][32];   // [buffer][warp][lane]

    const int tid   = threadIdx.x;
    const int wr    = tid >> 5;       // 0 or 1: which 4 heads
    const int lid   = tid & 31;
    const int batch = blockIdx.x;

    for (int i = tid; i < NWTS; i += 64) {
        float v;
        if      (i < 24)  v = wk[i];
        else if (i < 48)  v = wq[i - 24];
        else if (i < 72)  v = wv[i - 48];
        else if (i < 96)  v = Wp[i - 72];
        else if (i < 99)  v = bp[i - 96];
        else if (i < 111) v = W1[i - 99];
        else if (i < 123) v = b1[i - 111];
        else if (i < 135) v = W2[i - 123];
        else if (i < 138) v = b2[i - 135];
        else if (i == 138) v = w_lm[0];
        else               v = b_lm[0];
        W[i] = v;
    }

    float4 xv = reinterpret_cast<const float4*>(X + batch * NT)[lid];
    float x0 = xv.x, x1 = xv.y, x2 = xv.z, x3 = xv.w;
    __syncthreads();

    #pragma unroll
    for (int l = 0; l < NL; ++l) {
        const float u0 = x0*x0, u1 = x1*x1, u2 = x2*x2, u3 = x3*x3;

        float umx = fmaxf(fmaxf(u0, u1), fmaxf(u2, u3));
        float umn = fminf(fminf(u0, u1), fminf(u2, u3));
        #pragma unroll
        for (int o = 16; o > 0; o >>= 1) {
            umx = fmaxf(umx, __shfl_xor_sync(0xffffffffu, umx, o));
            umn = fminf(umn, __shfl_xor_sync(0xffffffffu, umn, o));
        }

        float c[4], coef[4], shi[4];
        bool fast = true;
        #pragma unroll
        for (int hh = 0; hh < 4; ++hh) {
            const int hg = wr * 4 + hh;
            c[hh]    = W[O_WK + l*NH + hg] * W[O_WQ + l*NH + hg] * LOG2E;
            coef[hh] = W[O_WV + l*NH + hg] * W[O_WP + l*NH + hg];
            float hi = (c[hh] > 0.0f) ? c[hh]*umx : c[hh]*umn;
            float lo = (c[hh] > 0.0f) ? c[hh]*umn : c[hh]*umx;
            shi[hh]  = hi;
            fast &= (hi - lo < 120.0f);
        }

        float py0 = 0.f, py1 = 0.f, py2 = 0.f, py3 = 0.f;

        if (fast) {
            // ---- 4 heads, single-window additive scans, stages interleaved ----
            float e0a[4], n0a[4], d01[4], m01[4], d012[4], m012[4], sd[4], sn[4];
            #pragma unroll
            for (int hh = 0; hh < 4; ++hh) {
                const float K  = shi[hh] - 63.0f;
                const float ch = c[hh];
                float e0 = ex2(fmaf(ch, u0, -K));
                float e1 = ex2(fmaf(ch, u1, -K));
                float e2 = ex2(fmaf(ch, u2, -K));
                float e3 = ex2(fmaf(ch, u3, -K));
                float n0 = e0*x0, n1 = e1*x1, n2 = e2*x2, n3 = e3*x3;
                float a  = e0 + e1;  float b_ = n0 + n1;
                float a2 = a + e2;   float b2_ = b_ + n2;
                e0a[hh] = e0;  n0a[hh] = n0;
                d01[hh] = a;   m01[hh] = b_;
                d012[hh] = a2; m012[hh] = b2_;
                sd[hh] = a2 + e3; sn[hh] = b2_ + n3;
            }
            #pragma unroll
            for (int o = 1; o < 32; o <<= 1) {
                float ud[4], un[4];
                #pragma unroll
                for (int hh = 0; hh < 4; ++hh) {
                    ud[hh] = __shfl_up_sync(0xffffffffu, sd[hh], o);
                    un[hh] = __shfl_up_sync(0xffffffffu, sn[hh], o);
                }
                if (lid >= o) {
                    #pragma unroll
                    for (int hh = 0; hh < 4; ++hh) { sd[hh] += ud[hh]; sn[hh] += un[hh]; }
                }
            }
            #pragma unroll
            for (int hh = 0; hh < 4; ++hh) {
                float Pd = __shfl_up_sync(0xffffffffu, sd[hh], 1);
                float Pn = __shfl_up_sync(0xffffffffu, sn[hh], 1);
                if (lid == 0) { Pd = 0.0f; Pn = 0.0f; }
                float h0 = (lid == 0) ? 0.0f : __fdividef(Pn, Pd);
                float h1 = __fdividef(Pn + n0a[hh],  Pd + e0a[hh]);
                float h2 = __fdividef(Pn + m01[hh],  Pd + d01[hh]);
                float h3 = __fdividef(Pn + m012[hh], Pd + d012[hh]);
                py0 = fmaf(h0, coef[hh], py0);
                py1 = fmaf(h1, coef[hh], py1);
                py2 = fmaf(h2, coef[hh], py2);
                py3 = fmaf(h3, coef[hh], py3);
            }
        } else {
            // ---- exact monoid fallback for all 4 heads ----
            #pragma unroll
            for (int hh = 0; hh < 4; ++hh) {
                const float ch = c[hh];
                OS a0 = { ch*u0, 1.0f, x0 };
                OS a1 = comb(a0, { ch*u1, 1.0f, x1 });
                OS a2 = comb(a1, { ch*u2, 1.0f, x2 });
                OS a3 = comb(a2, { ch*u3, 1.0f, x3 });
                OS agg = a3;
                #pragma unroll
                for (int o = 1; o < 32; o <<= 1) {
                    OS up;
                    up.m = __shfl_up_sync(0xffffffffu, agg.m, o);
                    up.d = __shfl_up_sync(0xffffffffu, agg.d, o);
                    up.n = __shfl_up_sync(0xffffffffu, agg.n, o);
                    if (lid >= o) agg = comb(up, agg);
                }
                OS P;
                P.m = __shfl_up_sync(0xffffffffu, agg.m, 1);
                P.d = __shfl_up_sync(0xffffffffu, agg.d, 1);
                P.n = __shfl_up_sync(0xffffffffu, agg.n, 1);
                if (lid == 0) { P.m = -1e30f; P.d = 0.0f; P.n = 0.0f; }
                OS q1 = comb(P, a0);
                OS q2 = comb(P, a1);
                OS q3 = comb(P, a2);
                float h0 = (lid == 0) ? 0.0f : __fdividef(P.n, P.d);
                py0 = fmaf(h0, coef[hh], py0);
                py1 = fmaf(__fdividef(q1.n, q1.d), coef[hh], py1);
                py2 = fmaf(__fdividef(q2.n, q2.d), coef[hh], py2);
                py3 = fmaf(__fdividef(q3.n, q3.d), coef[hh], py3);
            }
        }

        // ---- exchange partial y between the two warps (1 barrier, dbl-buffered) ----
        const int buf = l & 1;
        py[buf][wr][lid] = make_float4(py0, py1, py2, py3);
        __syncthreads();
        float4 other = py[buf][1 - wr][lid];
        const float bpv = W[O_BP + l];
        float y0 = py0 + other.x + bpv;
        float y1 = py1 + other.y + bpv;
        float y2 = py2 + other.z + bpv;
        float y3 = py3 + other.w + bpv;

        // ---- FF (redundant in both warps, register-local) ----
        const float b2v = W[O_B2 + l];
        const float w10 = W[O_W1 + l*4 + 0], w11 = W[O_W1 + l*4 + 1], w12 = W[O_W1 + l*4 + 2], w13 = W[O_W1 + l*4 + 3];
        const float b10 = W[O_B1 + l*4 + 0], b11 = W[O_B1 + l*4 + 1], b12 = W[O_B1 + l*4 + 2], b13 = W[O_B1 + l*4 + 3];
        const float w20 = W[O_W2 + l*4 + 0], w21 = W[O_W2 + l*4 + 1], w22 = W[O_W2 + l*4 + 2], w23 = W[O_W2 + l*4 + 3];
        #define FF(y_) ({                                                     \
            float f_ = b2v;                                                   \
            f_ = fmaf(fmaxf(fmaf((y_), w10, b10), 0.0f), w20, f_);            \
            f_ = fmaf(fmaxf(fmaf((y_), w11, b11), 0.0f), w21, f_);            \
            f_ = fmaf(fmaxf(fmaf((y_), w12, b12), 0.0f), w22, f_);            \
            f_ = fmaf(fmaxf(fmaf((y_), w13, b13), 0.0f), w23, f_);            \
            (y_) + f_; })
        x0 = FF(y0); x1 = FF(y1); x2 = FF(y2); x3 = FF(y3);
        #undef FF
    }

    if (wr == 0) {
        const float wl = W[O_WLM], bl = W[O_BLM];
        float4 ov;
        ov.x = fmaf(x0, wl, bl);
        ov.y = fmaf(x1, wl, bl);
        ov.z = fmaf(x2, wl, bl);
        ov.w = fmaf(x3, wl, bl);
        reinterpret_cast<float4*>(out + batch * NT)[lid] = ov;
    }
}

extern "C" void kernel_launch(void* const* d_in, const int* in_sizes, int n_in,
                              void* d_out, int out_size) {
    (void)in_sizes; (void)n_in; (void)out_size;
    cat_kernel<<<512, 64>>>(
        (const float*)d_in[0],  // X
        (const float*)d_in[1],  // wk
        (const float*)d_in[2],  // wq
        (const float*)d_in[3],  // wv
        (const float*)d_in[4],  // Wp
        (const float*)d_in[5],  // bp
        (const float*)d_in[6],  // W1
        (const float*)d_in[7],  // b1
        (const float*)d_in[8],  // W2
        (const float*)d_in[9],  // b2
        (const float*)d_in[10], // w_lm
        (const float*)d_in[11], // b_lm
        (float*)d_out);
}

// round 7
// speedup vs baseline: 1.4250x; 1.0250x over previous
#include <cuda_runtime.h>

#define NT 128
#define NH 8
#define NL 3
#define LOG2E 1.4426950408889634f

#define O_WK  0
#define O_WQ  24
#define O_WV  48
#define O_WP  72
#define O_BP  96
#define O_W1  99
#define O_B1  111
#define O_W2  123
#define O_B2  135
#define O_WLM 138
#define O_BLM 139
#define NWTS  140

__device__ __forceinline__ float ex2(float x) {
    float y;
    asm("ex2.approx.ftz.f32 %0, %1;" : "=f"(y) : "f"(x));
    return y;
}

struct OS { float m, d, n; };
__device__ __forceinline__ OS comb(OS a, OS b) {
    float mx = fmaxf(a.m, b.m);
    float mn = fminf(a.m, b.m);
    float e  = ex2(mn - mx);
    bool  bl = a.m < b.m;
    float sa = bl ? e : 1.0f;
    float sb = bl ? 1.0f : e;
    OS r; r.m = mx; r.d = fmaf(a.d, sa, b.d * sb); r.n = fmaf(a.n, sa, b.n * sb);
    return r;
}

__global__ __launch_bounds__(128) void cat_kernel(
    const float* __restrict__ X,
    const float* __restrict__ wk, const float* __restrict__ wq, const float* __restrict__ wv,
    const float* __restrict__ Wp, const float* __restrict__ bp,
    const float* __restrict__ W1, const float* __restrict__ b1,
    const float* __restrict__ W2, const float* __restrict__ b2,
    const float* __restrict__ w_lm, const float* __restrict__ b_lm,
    float* __restrict__ out)
{
    __shared__ float  W[NWTS];
    __shared__ float4 py[2][4][32];   // [buffer][warp][lane]

    const int tid   = threadIdx.x;
    const int wr    = tid >> 5;       // 0..3: which pair of heads
    const int lid   = tid & 31;
    const int batch = blockIdx.x;

    for (int i = tid; i < NWTS; i += 128) {
        float v;
        if      (i < 24)  v = wk[i];
        else if (i < 48)  v = wq[i - 24];
        else if (i < 72)  v = wv[i - 48];
        else if (i < 96)  v = Wp[i - 72];
        else if (i < 99)  v = bp[i - 96];
        else if (i < 111) v = W1[i - 99];
        else if (i < 123) v = b1[i - 111];
        else if (i < 135) v = W2[i - 123];
        else if (i < 138) v = b2[i - 135];
        else if (i == 138) v = w_lm[0];
        else               v = b_lm[0];
        W[i] = v;
    }

    float4 xv = reinterpret_cast<const float4*>(X + batch * NT)[lid];
    float x0 = xv.x, x1 = xv.y, x2 = xv.z, x3 = xv.w;
    __syncthreads();

    #pragma unroll
    for (int l = 0; l < NL; ++l) {
        const float u0 = x0*x0, u1 = x1*x1, u2 = x2*x2, u3 = x3*x3;

        // one butterfly max/min of u serves both heads of this warp
        float umx = fmaxf(fmaxf(u0, u1), fmaxf(u2, u3));
        float umn = fminf(fminf(u0, u1), fminf(u2, u3));
        #pragma unroll
        for (int o = 16; o > 0; o >>= 1) {
            umx = fmaxf(umx, __shfl_xor_sync(0xffffffffu, umx, o));
            umn = fminf(umn, __shfl_xor_sync(0xffffffffu, umn, o));
        }

        float c[2], coef[2], shi[2];
        bool fast = true;
        #pragma unroll
        for (int hh = 0; hh < 2; ++hh) {
            const int hg = wr * 2 + hh;
            c[hh]    = W[O_WK + l*NH + hg] * W[O_WQ + l*NH + hg] * LOG2E;
            coef[hh] = W[O_WV + l*NH + hg] * W[O_WP + l*NH + hg];
            float hi = (c[hh] > 0.0f) ? c[hh]*umx : c[hh]*umn;
            float lo = (c[hh] > 0.0f) ? c[hh]*umn : c[hh]*umx;
            shi[hh]  = hi;
            fast &= (hi - lo < 120.0f);
        }

        float py0 = 0.f, py1 = 0.f, py2 = 0.f, py3 = 0.f;

        if (fast) {
            // ---- 2 heads, single-window additive scans, stages interleaved ----
            float e0a[2], n0a[2], d01[2], m01[2], d012[2], m012[2], sd[2], sn[2];
            #pragma unroll
            for (int hh = 0; hh < 2; ++hh) {
                const float K  = shi[hh] - 63.0f;
                const float ch = c[hh];
                float e0 = ex2(fmaf(ch, u0, -K));
                float e1 = ex2(fmaf(ch, u1, -K));
                float e2 = ex2(fmaf(ch, u2, -K));
                float e3 = ex2(fmaf(ch, u3, -K));
                float n0 = e0*x0, n1 = e1*x1, n2 = e2*x2, n3 = e3*x3;
                float a  = e0 + e1;  float b_ = n0 + n1;
                float a2 = a + e2;   float b2_ = b_ + n2;
                e0a[hh] = e0;  n0a[hh] = n0;
                d01[hh] = a;   m01[hh] = b_;
                d012[hh] = a2; m012[hh] = b2_;
                sd[hh] = a2 + e3; sn[hh] = b2_ + n3;
            }
            #pragma unroll
            for (int o = 1; o < 32; o <<= 1) {
                float ud0 = __shfl_up_sync(0xffffffffu, sd[0], o);
                float un0 = __shfl_up_sync(0xffffffffu, sn[0], o);
                float ud1 = __shfl_up_sync(0xffffffffu, sd[1], o);
                float un1 = __shfl_up_sync(0xffffffffu, sn[1], o);
                if (lid >= o) {
                    sd[0] += ud0; sn[0] += un0;
                    sd[1] += ud1; sn[1] += un1;
                }
            }
            #pragma unroll
            for (int hh = 0; hh < 2; ++hh) {
                float Pd = __shfl_up_sync(0xffffffffu, sd[hh], 1);
                float Pn = __shfl_up_sync(0xffffffffu, sn[hh], 1);
                if (lid == 0) { Pd = 0.0f; Pn = 0.0f; }
                float h0 = (lid == 0) ? 0.0f : __fdividef(Pn, Pd);
                float h1 = __fdividef(Pn + n0a[hh],  Pd + e0a[hh]);
                float h2 = __fdividef(Pn + m01[hh],  Pd + d01[hh]);
                float h3 = __fdividef(Pn + m012[hh], Pd + d012[hh]);
                py0 = fmaf(h0, coef[hh], py0);
                py1 = fmaf(h1, coef[hh], py1);
                py2 = fmaf(h2, coef[hh], py2);
                py3 = fmaf(h3, coef[hh], py3);
            }
        } else {
            // ---- exact monoid fallback for both heads ----
            #pragma unroll
            for (int hh = 0; hh < 2; ++hh) {
                const float ch = c[hh];
                OS a0 = { ch*u0, 1.0f, x0 };
                OS a1 = comb(a0, { ch*u1, 1.0f, x1 });
                OS a2 = comb(a1, { ch*u2, 1.0f, x2 });
                OS a3 = comb(a2, { ch*u3, 1.0f, x3 });
                OS agg = a3;
                #pragma unroll
                for (int o = 1; o < 32; o <<= 1) {
                    OS up;
                    up.m = __shfl_up_sync(0xffffffffu, agg.m, o);
                    up.d = __shfl_up_sync(0xffffffffu, agg.d, o);
                    up.n = __shfl_up_sync(0xffffffffu, agg.n, o);
                    if (lid >= o) agg = comb(up, agg);
                }
                OS P;
                P.m = __shfl_up_sync(0xffffffffu, agg.m, 1);
                P.d = __shfl_up_sync(0xffffffffu, agg.d, 1);
                P.n = __shfl_up_sync(0xffffffffu, agg.n, 1);
                if (lid == 0) { P.m = -1e30f; P.d = 0.0f; P.n = 0.0f; }
                OS q1 = comb(P, a0);
                OS q2 = comb(P, a1);
                OS q3 = comb(P, a2);
                float h0 = (lid == 0) ? 0.0f : __fdividef(P.n, P.d);
                py0 = fmaf(h0, coef[hh], py0);
                py1 = fmaf(__fdividef(q1.n, q1.d), coef[hh], py1);
                py2 = fmaf(__fdividef(q2.n, q2.d), coef[hh], py2);
                py3 = fmaf(__fdividef(q3.n, q3.d), coef[hh], py3);
            }
        }

        // ---- exchange partial y among 4 warps (1 barrier, dbl-buffered) ----
        const int buf = l & 1;
        py[buf][wr][lid] = make_float4(py0, py1, py2, py3);
        __syncthreads();
        const float bpv = W[O_BP + l];
        float4 pa = py[buf][0][lid];
        float4 pb = py[buf][1][lid];
        float4 pc = py[buf][2][lid];
        float4 pd = py[buf][3][lid];
        float y0 = (pa.x + pb.x) + (pc.x + pd.x) + bpv;
        float y1 = (pa.y + pb.y) + (pc.y + pd.y) + bpv;
        float y2 = (pa.z + pb.z) + (pc.z + pd.z) + bpv;
        float y3 = (pa.w + pb.w) + (pc.w + pd.w) + bpv;

        // ---- FF (redundant in all warps, register-local) ----
        const float b2v = W[O_B2 + l];
        const float w10 = W[O_W1 + l*4 + 0], w11 = W[O_W1 + l*4 + 1], w12 = W[O_W1 + l*4 + 2], w13 = W[O_W1 + l*4 + 3];
        const float b10 = W[O_B1 + l*4 + 0], b11 = W[O_B1 + l*4 + 1], b12 = W[O_B1 + l*4 + 2], b13 = W[O_B1 + l*4 + 3];
        const float w20 = W[O_W2 + l*4 + 0], w21 = W[O_W2 + l*4 + 1], w22 = W[O_W2 + l*4 + 2], w23 = W[O_W2 + l*4 + 3];
        #define FF(y_) ({                                                     \
            float f_ = b2v;                                                   \
            f_ = fmaf(fmaxf(fmaf((y_), w10, b10), 0.0f), w20, f_);            \
            f_ = fmaf(fmaxf(fmaf((y_), w11, b11), 0.0f), w21, f_);            \
            f_ = fmaf(fmaxf(fmaf((y_), w12, b12), 0.0f), w22, f_);            \
            f_ = fmaf(fmaxf(fmaf((y_), w13, b13), 0.0f), w23, f_);            \
            (y_) + f_; })
        x0 = FF(y0); x1 = FF(y1); x2 = FF(y2); x3 = FF(y3);
        #undef FF
    }

    if (wr == 0) {
        const float wl = W[O_WLM], bl = W[O_BLM];
        float4 ov;
        ov.x = fmaf(x0, wl, bl);
        ov.y = fmaf(x1, wl, bl);
        ov.z = fmaf(x2, wl, bl);
        ov.w = fmaf(x3, wl, bl);
        reinterpret_cast<float4*>(out + batch * NT)[lid] = ov;
    }
}

extern "C" void kernel_launch(void* const* d_in, const int* in_sizes, int n_in,
                              void* d_out, int out_size) {
    (void)in_sizes; (void)n_in; (void)out_size;
    cat_kernel<<<512, 128>>>(
        (const float*)d_in[0],  // X
        (const float*)d_in[1],  // wk
        (const float*)d_in[2],  // wq
        (const float*)d_in[3],  // wv
        (const float*)d_in[4],  // Wp
        (const float*)d_in[5],  // bp
        (const float*)d_in[6],  // W1
        (const float*)d_in[7],  // b1
        (const float*)d_in[8],  // W2
        (const float*)d_in[9],  // b2
        (const float*)d_in[10], // w_lm
        (const float*)d_in[11], // b_lm
        (float*)d_out);
}